// round 7
// baseline (speedup 1.0000x reference)
#include <cuda_runtime.h>
#include <math.h>

#define N_ROWS 8192
#define D 512
#define C 64
#define NSEG 8
#define SEG (N_ROWS / NSEG)   // 1024
#define FULL 0xffffffffu

// ---------------- scratch (device globals; no allocation) ----------------
__device__ int    g_lbl[N_ROWS];
__device__ float  g_Mpart[C][NSEG][D];             // per-class per-segment vector sums
__device__ float  g_Spart[C][NSEG];
__device__ int    g_cntpart[C][NSEG];
__device__ unsigned short g_classlist[C][NSEG][SEG]; // per-(class,seg) row ids (4MB)
__device__ int    g_cnt[C];
__device__ double g_same_sum;
__device__ unsigned long long g_same_pairs;
__device__ double g_hinge;
__device__ int    g_done;

// ---------------- K0: argmax of labels, zero accumulators ----------------
__global__ void k0_argmax(const float* __restrict__ labels) {
    if (blockIdx.x == 0 && threadIdx.x == 0) {
        g_same_sum = 0.0; g_same_pairs = 0ull; g_hinge = 0.0; g_done = 0;
    }
    int lane = threadIdx.x & 31;
    int warp = (blockIdx.x * blockDim.x + threadIdx.x) >> 5;
    int nwarps = gridDim.x * (blockDim.x >> 5);
    for (int r = warp; r < N_ROWS; r += nwarps) {
        float v0 = labels[r * C + lane];
        float v1 = labels[r * C + lane + 32];
        float v; int idx;
        if (v1 > v0) { v = v1; idx = lane + 32; } else { v = v0; idx = lane; }
        #pragma unroll
        for (int off = 16; off; off >>= 1) {
            float ov = __shfl_xor_sync(FULL, v, off);
            int   oi = __shfl_xor_sync(FULL, idx, off);
            if (ov > v || (ov == v && oi < idx)) { v = ov; idx = oi; }
        }
        if (lane == 0) g_lbl[r] = idx;
    }
}

// ---------------- K1: per-class, per-segment sums + persist lists --------
__global__ void k1_classsum(const float2* __restrict__ X2) {
    int c = blockIdx.x;        // class
    int s = blockIdx.y;        // segment
    int tid = threadIdx.x;     // 256 threads; thread t owns coords 2t, 2t+1
    __shared__ int   mlist[SEG];
    __shared__ int   mcount;
    __shared__ float red[256];

    if (tid == 0) mcount = 0;
    __syncthreads();
    int base = s * SEG;
    for (int j = tid; j < SEG; j += 256)
        if (g_lbl[base + j] == c) mlist[atomicAdd(&mcount, 1)] = base + j;
    __syncthreads();

    int cnt = mcount;
    // persist the compacted list for k4 (total writes across grid = 8192)
    for (int j = tid; j < cnt; j += 256)
        g_classlist[c][s][j] = (unsigned short)mlist[j];

    float mx = 0.f, my = 0.f, ss = 0.f;
    int k = 0;
    for (; k + 4 <= cnt; k += 4) {
        int i0 = mlist[k], i1 = mlist[k+1], i2 = mlist[k+2], i3 = mlist[k+3];
        float2 a = X2[i0 * 256 + tid];
        float2 b = X2[i1 * 256 + tid];
        float2 e = X2[i2 * 256 + tid];
        float2 d = X2[i3 * 256 + tid];
        mx += a.x + b.x + e.x + d.x;
        my += a.y + b.y + e.y + d.y;
        ss += a.x*a.x + a.y*a.y + b.x*b.x + b.y*b.y
            + e.x*e.x + e.y*e.y + d.x*d.x + d.y*d.y;
    }
    for (; k < cnt; k++) {
        float2 a = X2[mlist[k] * 256 + tid];
        mx += a.x; my += a.y; ss += a.x*a.x + a.y*a.y;
    }

    ((float2*)g_Mpart[c][s])[tid] = make_float2(mx, my);

    red[tid] = ss; __syncthreads();
    for (int o = 128; o; o >>= 1) { if (tid < o) red[tid] += red[tid + o]; __syncthreads(); }
    if (tid == 0) { g_Spart[c][s] = red[0]; g_cntpart[c][s] = cnt; }
}

// ---------------- K2: per-class reduce -> cnt*S - ||M||^2 ----------------
__global__ void k2_reduce() {
    int c = blockIdx.x, tid = threadIdx.x;
    __shared__ float red[256];
    float mx = 0.f, my = 0.f;
    #pragma unroll
    for (int s = 0; s < NSEG; s++) {
        float2 v = ((const float2*)g_Mpart[c][s])[tid];
        mx += v.x; my += v.y;
    }
    red[tid] = mx * mx + my * my;
    __syncthreads();
    for (int o = 128; o; o >>= 1) { if (tid < o) red[tid] += red[tid + o]; __syncthreads(); }
    if (tid == 0) {
        float S = 0.f; int cnt = 0;
        #pragma unroll
        for (int s = 0; s < NSEG; s++) { S += g_Spart[c][s]; cnt += g_cntpart[c][s]; }
        g_cnt[c] = cnt;
        if (cnt > 1) {
            double same_c = (double)cnt * (double)S - (double)red[0];
            atomicAdd(&g_same_sum, same_c);
        }
        unsigned long long p = (unsigned long long)cnt * (unsigned long long)(cnt - 1) / 2ull;
        if (p) atomicAdd(&g_same_pairs, p);
    }
}

// ---------------- K4: lists-from-k1 + bipartite hinge + finalize ---------
// m1/m2 via ballot; lists gathered from g_classlist (no scan, no atomics).
// B list at lst[0..nB), A list entry e at lst[N_ROWS-1-e].
#define TA 8
#define TBC 16
__global__ void k4_cross(const float4* __restrict__ X4, float* __restrict__ out) {
    __shared__ unsigned short lst[N_ROWS];   // 16KB: B grows up, A grows down
    __shared__ int offA[NSEG], offB[NSEG], cA[NSEG], cB[NSEG];
    __shared__ float4 Asm[TA][128];          // 8 rows x 512 floats = 16KB
    __shared__ float  sqAs[TA];
    int tid = threadIdx.x, warp = tid >> 5, lane = tid & 31;

    // --- m1/m2 via 2 loads + ballots ---
    int clo = g_cnt[lane & 31];
    int chi = g_cnt[(lane & 31) + 32];
    unsigned blo = __ballot_sync(FULL, clo > 0);
    unsigned bhi = __ballot_sync(FULL, chi > 0);
    int m1 = -1, m2 = -1;
    if (bhi) { int b = 31 - __clz(bhi); m1 = 32 + b; bhi &= ~(1u << b); }
    else if (blo) { int b = 31 - __clz(blo); m1 = b; blo &= ~(1u << b); }
    if (bhi)      m2 = 32 + (31 - __clz(bhi));
    else if (blo) m2 = 31 - __clz(blo);

    // --- segment offsets (thread 0; 16 cached loads) ---
    if (tid == 0) {
        int oa = 0, ob = 0;
        #pragma unroll
        for (int s = 0; s < NSEG; s++) {
            int ca = (m2 >= 0) ? g_cntpart[m2][s] : 0;
            int cb = (m1 >= 0) ? g_cntpart[m1][s] : 0;
            offA[s] = oa; cA[s] = ca; oa += ca;
            offB[s] = ob; cB[s] = cb; ob += cb;
        }
    }
    __syncthreads();
    int nA = offA[NSEG-1] + cA[NSEG-1];
    int nB = offB[NSEG-1] + cB[NSEG-1];

    // --- gather lists from g_classlist (coalesced, ~nA+nB total loads) ---
    #pragma unroll
    for (int s = 0; s < NSEG; s++) {
        int ca = cA[s], oa = offA[s];
        for (int j = tid; j < ca; j += 256)
            lst[N_ROWS - 1 - (oa + j)] = g_classlist[m2][s][j];
        int cb = cB[s], ob = offB[s];
        for (int j = tid; j < cb; j += 256)
            lst[ob + j] = g_classlist[m1][s][j];
    }
    __syncthreads();

    double hacc = 0.0;
    if (nA > 0 && nB > 0) {
        int tilesA = (nA + TA - 1) / TA;
        int tilesB = (nB + TBC - 1) / TBC;
        int ntiles = tilesA * tilesB;

        for (int t = blockIdx.x; t < ntiles; t += gridDim.x) {
            int ta = t / tilesB, tb = t % tilesB;
            __syncthreads();                    // protect Asm across iterations
            int ae = ta * TA + warp;
            float sqa = 0.f;
            if (ae < nA) {
                int row = lst[N_ROWS - 1 - ae];
                #pragma unroll
                for (int k = 0; k < 4; k++) {
                    float4 v = X4[row * 128 + lane + 32 * k];
                    Asm[warp][lane + 32 * k] = v;
                    sqa += v.x*v.x + v.y*v.y + v.z*v.z + v.w*v.w;
                }
            } else {
                #pragma unroll
                for (int k = 0; k < 4; k++)
                    Asm[warp][lane + 32 * k] = make_float4(0.f, 0.f, 0.f, 0.f);
            }
            #pragma unroll
            for (int off = 16; off; off >>= 1) sqa += __shfl_xor_sync(FULL, sqa, off);
            if (lane == 0) sqAs[warp] = sqa;
            __syncthreads();

            int aCnt = min(TA, nA - ta * TA);
            int bLo = tb * TBC, bHi = min(bLo + TBC, nB);
            for (int bi = bLo + warp; bi < bHi; bi += 8) {
                int brow = lst[bi];
                float4 vb[4];
                float sqb = 0.f;
                #pragma unroll
                for (int k = 0; k < 4; k++) {
                    vb[k] = X4[brow * 128 + lane + 32 * k];
                    sqb += vb[k].x*vb[k].x + vb[k].y*vb[k].y
                         + vb[k].z*vb[k].z + vb[k].w*vb[k].w;
                }
                float dots[TA];
                #pragma unroll
                for (int a = 0; a < TA; a++) {
                    float d = 0.f;
                    #pragma unroll
                    for (int k = 0; k < 4; k++) {
                        float4 va = Asm[a][lane + 32 * k];
                        d += va.x*vb[k].x + va.y*vb[k].y + va.z*vb[k].z + va.w*vb[k].w;
                    }
                    dots[a] = d;
                }
                #pragma unroll
                for (int off = 16; off; off >>= 1) sqb += __shfl_xor_sync(FULL, sqb, off);
                #pragma unroll
                for (int a = 0; a < TA; a++) {
                    float d = dots[a];
                    #pragma unroll
                    for (int off = 16; off; off >>= 1) d += __shfl_xor_sync(FULL, d, off);
                    dots[a] = d;
                }
                if (lane == 0) {
                    #pragma unroll
                    for (int a = 0; a < TA; a++) {
                        if (a < aCnt) {
                            float d2 = fmaxf(sqAs[a] + sqb - 2.f * dots[a], 0.f);
                            if (d2 < 1.0f) {        // hinge active iff sqrt(d2) < MARGIN
                                float h = 1.0f - sqrtf(d2);
                                hacc += (double)(h * h);
                            }
                        }
                    }
                }
            }
        }
    }
    if (lane == 0 && hacc != 0.0) atomicAdd(&g_hinge, hacc);

    // --- finalize: last block writes the scalar ---
    __threadfence();
    __syncthreads();
    if (tid == 0) {
        int prev = atomicAdd(&g_done, 1);
        if (prev == (int)gridDim.x - 1) {
            double same = g_same_sum / (double)g_same_pairs;
            double total_pairs = (double)((long long)N_ROWS * (N_ROWS - 1) / 2);
            out[0] = (float)(same + g_hinge / total_pairs);
            g_done = 0;
        }
    }
}

// ---------------- launch ----------------
extern "C" void kernel_launch(void* const* d_in, const int* in_sizes, int n_in,
                              void* d_out, int out_size) {
    const float* X      = (const float*)d_in[0];   // [8192, 512] f32
    const float* labels = (const float*)d_in[1];   // [8192, 64]  f32
    (void)in_sizes; (void)n_in; (void)out_size;

    k0_argmax<<<128, 256>>>(labels);
    dim3 g1(C, NSEG);
    k1_classsum<<<g1, 256>>>((const float2*)X);
    k2_reduce<<<C, 256>>>();
    k4_cross<<<128, 256>>>((const float4*)X, (float*)d_out);
}

// round 8
// speedup vs baseline: 1.0145x; 1.0145x over previous
#include <cuda_runtime.h>
#include <math.h>

#define N_ROWS 8192
#define D 512
#define C 64
#define NSEG 8
#define SEG (N_ROWS / NSEG)   // 1024
#define FULL 0xffffffffu

// ---------------- scratch (device globals; no allocation) ----------------
__device__ int    g_lbl[N_ROWS];
__device__ float  g_Mpart[C][NSEG][D];               // per-class per-segment vector sums
__device__ float  g_Spart[C][NSEG];
__device__ int    g_cntpart[C][NSEG];
__device__ unsigned short g_classlist[C][NSEG][SEG]; // per-(class,seg) row ids
__device__ unsigned short g_listA[N_ROWS], g_listB[N_ROWS]; // flat cross lists
__device__ int    g_nA, g_nB;
__device__ double g_same_sum;
__device__ unsigned long long g_same_pairs;
__device__ double g_hinge;

// ---------------- K0: argmax of labels, zero accumulators ----------------
__global__ void k0_argmax(const float* __restrict__ labels) {
    if (blockIdx.x == 0 && threadIdx.x == 0) {
        g_same_sum = 0.0; g_same_pairs = 0ull; g_hinge = 0.0;
        g_nA = 0; g_nB = 0;
    }
    int lane = threadIdx.x & 31;
    int warp = (blockIdx.x * blockDim.x + threadIdx.x) >> 5;
    int nwarps = gridDim.x * (blockDim.x >> 5);
    for (int r = warp; r < N_ROWS; r += nwarps) {
        float v0 = labels[r * C + lane];
        float v1 = labels[r * C + lane + 32];
        float v; int idx;
        if (v1 > v0) { v = v1; idx = lane + 32; } else { v = v0; idx = lane; }
        #pragma unroll
        for (int off = 16; off; off >>= 1) {
            float ov = __shfl_xor_sync(FULL, v, off);
            int   oi = __shfl_xor_sync(FULL, idx, off);
            if (ov > v || (ov == v && oi < idx)) { v = ov; idx = oi; }
        }
        if (lane == 0) g_lbl[r] = idx;
    }
}

// ---------------- K1: per-class, per-segment sums + persist lists --------
__global__ void k1_classsum(const float2* __restrict__ X2) {
    int c = blockIdx.x;        // class
    int s = blockIdx.y;        // segment
    int tid = threadIdx.x;     // 256 threads; thread t owns coords 2t, 2t+1
    __shared__ int   mlist[SEG];
    __shared__ int   mcount;
    __shared__ float red[256];

    if (tid == 0) mcount = 0;
    __syncthreads();
    int base = s * SEG;
    for (int j = tid; j < SEG; j += 256)
        if (g_lbl[base + j] == c) mlist[atomicAdd(&mcount, 1)] = base + j;
    __syncthreads();

    int cnt = mcount;
    for (int j = tid; j < cnt; j += 256)
        g_classlist[c][s][j] = (unsigned short)mlist[j];

    float mx = 0.f, my = 0.f, ss = 0.f;
    int k = 0;
    for (; k + 4 <= cnt; k += 4) {
        int i0 = mlist[k], i1 = mlist[k+1], i2 = mlist[k+2], i3 = mlist[k+3];
        float2 a = X2[i0 * 256 + tid];
        float2 b = X2[i1 * 256 + tid];
        float2 e = X2[i2 * 256 + tid];
        float2 d = X2[i3 * 256 + tid];
        mx += a.x + b.x + e.x + d.x;
        my += a.y + b.y + e.y + d.y;
        ss += a.x*a.x + a.y*a.y + b.x*b.x + b.y*b.y
            + e.x*e.x + e.y*e.y + d.x*d.x + d.y*d.y;
    }
    for (; k < cnt; k++) {
        float2 a = X2[mlist[k] * 256 + tid];
        mx += a.x; my += a.y; ss += a.x*a.x + a.y*a.y;
    }

    ((float2*)g_Mpart[c][s])[tid] = make_float2(mx, my);

    red[tid] = ss; __syncthreads();
    for (int o = 128; o; o >>= 1) { if (tid < o) red[tid] += red[tid + o]; __syncthreads(); }
    if (tid == 0) { g_Spart[c][s] = red[0]; g_cntpart[c][s] = cnt; }
}

// ------- K2: blocks 0..63 = per-class reduce; block 64 = build lists -----
__global__ void k2_reduce() {
    int tid = threadIdx.x;
    if (blockIdx.x < C) {
        int c = blockIdx.x;
        __shared__ float red[256];
        float mx = 0.f, my = 0.f;
        #pragma unroll
        for (int s = 0; s < NSEG; s++) {
            float2 v = ((const float2*)g_Mpart[c][s])[tid];
            mx += v.x; my += v.y;
        }
        red[tid] = mx * mx + my * my;
        __syncthreads();
        for (int o = 128; o; o >>= 1) { if (tid < o) red[tid] += red[tid + o]; __syncthreads(); }
        if (tid == 0) {
            float S = 0.f; int cnt = 0;
            #pragma unroll
            for (int s = 0; s < NSEG; s++) { S += g_Spart[c][s]; cnt += g_cntpart[c][s]; }
            if (cnt > 1) {
                double same_c = (double)cnt * (double)S - (double)red[0];
                atomicAdd(&g_same_sum, same_c);
            }
            unsigned long long p = (unsigned long long)cnt * (unsigned long long)(cnt - 1) / 2ull;
            if (p) atomicAdd(&g_same_pairs, p);
        }
    } else {
        // ---- list-builder block: m1/m2 + flatten classlists ----
        __shared__ int s_pres[C];
        __shared__ int offA[NSEG], offB[NSEG], cA[NSEG], cB[NSEG];
        __shared__ int s_m1, s_m2;
        if (tid < C) {
            int tot = 0;
            #pragma unroll
            for (int s = 0; s < NSEG; s++) tot += g_cntpart[tid][s];
            s_pres[tid] = (tot > 0);
        }
        __syncthreads();
        if (tid < 32) {
            int lane = tid;
            unsigned blo = __ballot_sync(FULL, s_pres[lane] != 0);
            unsigned bhi = __ballot_sync(FULL, s_pres[lane + 32] != 0);
            int m1 = -1, m2 = -1;
            if (bhi) { int b = 31 - __clz(bhi); m1 = 32 + b; bhi &= ~(1u << b); }
            else if (blo) { int b = 31 - __clz(blo); m1 = b; blo &= ~(1u << b); }
            if (bhi)      m2 = 32 + (31 - __clz(bhi));
            else if (blo) m2 = 31 - __clz(blo);
            if (lane == 0) { s_m1 = m1; s_m2 = m2; }
        }
        __syncthreads();
        int m1 = s_m1, m2 = s_m2;
        if (tid == 0) {
            int oa = 0, ob = 0;
            #pragma unroll
            for (int s = 0; s < NSEG; s++) {
                int ca = (m2 >= 0) ? g_cntpart[m2][s] : 0;
                int cb = (m1 >= 0) ? g_cntpart[m1][s] : 0;
                offA[s] = oa; cA[s] = ca; oa += ca;
                offB[s] = ob; cB[s] = cb; ob += cb;
            }
            g_nA = oa; g_nB = ob;
        }
        __syncthreads();
        int mm2 = (m2 >= 0) ? m2 : 0;
        int mm1 = (m1 >= 0) ? m1 : 0;
        #pragma unroll
        for (int s = 0; s < NSEG; s++) {
            int ca = cA[s], oa = offA[s];
            for (int j = tid; j < ca; j += 256) g_listA[oa + j] = g_classlist[mm2][s][j];
            int cb = cB[s], ob = offB[s];
            for (int j = tid; j < cb; j += 256) g_listB[ob + j] = g_classlist[mm1][s][j];
        }
    }
}

// ---------------- K4: bipartite hinge, short latency ladder --------------
// header (nA,nB) -> row ids -> X rows -> smem tile compute -> hinge atomic
#define TA 8
#define TBC 16
__global__ void k4_cross(const float4* __restrict__ X4) {
    __shared__ float4 Asm[TA][128];          // 8 rows x 512 floats = 16KB
    __shared__ float  sqAs[TA];
    int tid = threadIdx.x, warp = tid >> 5, lane = tid & 31;

    int nA = g_nA, nB = g_nB;                // RT1: header
    if (nA == 0 || nB == 0) return;
    int tilesA = (nA + TA - 1) / TA;
    int tilesB = (nB + TBC - 1) / TBC;
    int ntiles = tilesA * tilesB;
    double hacc = 0.0;

    for (int t = blockIdx.x; t < ntiles; t += gridDim.x) {
        int ta = t / tilesB, tb = t % tilesB;
        __syncthreads();                     // protect Asm across iterations
        int ae = ta * TA + warp;
        bool avalid = (ae < nA);
        int arow = avalid ? (int)g_listA[ae] : 0;            // RT2a: id
        int bi0 = tb * TBC + warp, bi1 = bi0 + 8;
        int brow0 = (bi0 < nB) ? (int)g_listB[bi0] : 0;      // RT2b: ids
        int brow1 = (bi1 < nB) ? (int)g_listB[bi1] : 0;

        float sqa = 0.f;
        if (avalid) {
            #pragma unroll
            for (int k = 0; k < 4; k++) {                    // RT3: X rows
                float4 v = X4[arow * 128 + lane + 32 * k];
                Asm[warp][lane + 32 * k] = v;
                sqa += v.x*v.x + v.y*v.y + v.z*v.z + v.w*v.w;
            }
        } else {
            #pragma unroll
            for (int k = 0; k < 4; k++)
                Asm[warp][lane + 32 * k] = make_float4(0.f, 0.f, 0.f, 0.f);
        }
        #pragma unroll
        for (int off = 16; off; off >>= 1) sqa += __shfl_xor_sync(FULL, sqa, off);
        if (lane == 0) sqAs[warp] = sqa;
        __syncthreads();

        int aCnt = min(TA, nA - ta * TA);
        #pragma unroll
        for (int u = 0; u < 2; u++) {
            int bi   = u ? bi1 : bi0;
            int brow = u ? brow1 : brow0;
            if (bi >= nB) continue;
            float4 vb[4];
            float sqb = 0.f;
            #pragma unroll
            for (int k = 0; k < 4; k++) {
                vb[k] = X4[brow * 128 + lane + 32 * k];
                sqb += vb[k].x*vb[k].x + vb[k].y*vb[k].y
                     + vb[k].z*vb[k].z + vb[k].w*vb[k].w;
            }
            float dots[TA];
            #pragma unroll
            for (int a = 0; a < TA; a++) {
                float d = 0.f;
                #pragma unroll
                for (int k = 0; k < 4; k++) {
                    float4 va = Asm[a][lane + 32 * k];
                    d += va.x*vb[k].x + va.y*vb[k].y + va.z*vb[k].z + va.w*vb[k].w;
                }
                dots[a] = d;
            }
            #pragma unroll
            for (int off = 16; off; off >>= 1) sqb += __shfl_xor_sync(FULL, sqb, off);
            #pragma unroll
            for (int a = 0; a < TA; a++) {
                float d = dots[a];
                #pragma unroll
                for (int off = 16; off; off >>= 1) d += __shfl_xor_sync(FULL, d, off);
                dots[a] = d;
            }
            if (lane == 0) {
                #pragma unroll
                for (int a = 0; a < TA; a++) {
                    if (a < aCnt) {
                        float d2 = fmaxf(sqAs[a] + sqb - 2.f * dots[a], 0.f);
                        if (d2 < 1.0f) {        // hinge active iff sqrt(d2) < MARGIN
                            float h = 1.0f - sqrtf(d2);
                            hacc += (double)(h * h);
                        }
                    }
                }
            }
        }
    }
    if (lane == 0 && hacc != 0.0) atomicAdd(&g_hinge, hacc);
}

// ---------------- K5: finalize scalar ----------------
__global__ void k5_final(float* __restrict__ out) {
    double same = g_same_sum / (double)g_same_pairs;
    double total_pairs = (double)((long long)N_ROWS * (N_ROWS - 1) / 2);
    out[0] = (float)(same + g_hinge / total_pairs);
}

// ---------------- launch ----------------
extern "C" void kernel_launch(void* const* d_in, const int* in_sizes, int n_in,
                              void* d_out, int out_size) {
    const float* X      = (const float*)d_in[0];   // [8192, 512] f32
    const float* labels = (const float*)d_in[1];   // [8192, 64]  f32
    (void)in_sizes; (void)n_in; (void)out_size;

    k0_argmax<<<128, 256>>>(labels);
    dim3 g1(C, NSEG);
    k1_classsum<<<g1, 256>>>((const float2*)X);
    k2_reduce<<<C + 1, 256>>>();
    k4_cross<<<128, 256>>>((const float4*)X);
    k5_final<<<1, 1>>>((float*)d_out);
}